// round 5
// baseline (speedup 1.0000x reference)
#include <cuda_runtime.h>
#include <cuda_bf16.h>
#include <math.h>

#define NNODES 49152
#define NEDGES 196608
#define NGRAPH 1024
#define SNODES 48
#define DFEAT  256
#define GD     512
#define NBLK   192      // NNODES / 256

// ---------------- scratch (static __device__: no allocations allowed) ----------------
__device__ float    g_A [(size_t)NNODES * 512];   // fp32 [x | lap] (512 feats per node)
__device__ unsigned g_Ah[(size_t)NNODES * 512];   // split A [N,1024 feats]: cols 0:512 mean1, 512:768 x, 768:1024 lap
__device__ unsigned g_Al[(size_t)NNODES * 512];
__device__ unsigned g_Hh[(size_t)NNODES * 256];   // h [N,512] split
__device__ unsigned g_Hl[(size_t)NNODES * 256];
__device__ unsigned g_A2h[(size_t)NGRAPH * 512];  // A2 [B,1024]: [pool(mean2) | pool(h)]
__device__ unsigned g_A2l[(size_t)NGRAPH * 512];
__device__ unsigned g_W1h[512 * 512], g_W1l[512 * 512];
__device__ unsigned g_W2h[512 * 512], g_W2l[512 * 512];
__device__ int   g_deg [NNODES];
__device__ int   g_cnt [NNODES];
__device__ int   g_roff[NNODES + 1];
__device__ int   g_coff[NNODES + 1];
__device__ int   g_curr[NNODES];
__device__ int   g_curc[NNODES];
__device__ int   g_rnbr[NEDGES];
__device__ int   g_cnbr[NEDGES];
__device__ float g_rw  [NEDGES];
__device__ float g_dinv[NNODES];
__device__ int   g_bsum[2 * (NBLK + 1)];
__device__ int   g_gcnt[NGRAPH];
__device__ int   g_gcur[NGRAPH];
__device__ int   g_goff[NGRAPH + 1];
__device__ int   g_gsrc[NEDGES];
__device__ float g_gwt [NEDGES];
__device__ int   g_is64;

// ---------------- helpers ----------------
static __device__ __forceinline__ float4 f4fma(float4 a, float w, float4 b) {
    a.x = fmaf(w, b.x, a.x); a.y = fmaf(w, b.y, a.y);
    a.z = fmaf(w, b.z, a.z); a.w = fmaf(w, b.w, a.w); return a;
}
static __device__ __forceinline__ int edge_at(const int* __restrict__ w, int idx) {
    return g_is64 ? w[2 * idx] : w[idx];
}
static __device__ __forceinline__ unsigned pack_hi_lo(float x, float y, unsigned& lo) {
    __nv_bfloat16 hx = __float2bfloat16(x);
    __nv_bfloat16 hy = __float2bfloat16(y);
    float rx = x - __bfloat162float(hx);
    float ry = y - __bfloat162float(hy);
    __nv_bfloat16 lx = __float2bfloat16(rx);
    __nv_bfloat16 ly = __float2bfloat16(ry);
    lo = (unsigned)__bfloat16_as_ushort(lx) | ((unsigned)__bfloat16_as_ushort(ly) << 16);
    return (unsigned)__bfloat16_as_ushort(hx) | ((unsigned)__bfloat16_as_ushort(hy) << 16);
}
static __device__ __forceinline__ float2 unpk2(unsigned h, unsigned l) {
    __nv_bfloat162 hb = *reinterpret_cast<__nv_bfloat162*>(&h);
    __nv_bfloat162 lb = *reinterpret_cast<__nv_bfloat162*>(&l);
    return make_float2(__bfloat162float(hb.x) + __bfloat162float(lb.x),
                       __bfloat162float(hb.y) + __bfloat162float(lb.y));
}

#define MMA_BF16(c, a0, a1, a2, a3, b0, b1)                                           \
    asm volatile(                                                                      \
        "mma.sync.aligned.m16n8k16.row.col.f32.bf16.bf16.f32 "                         \
        "{%0,%1,%2,%3},{%4,%5,%6,%7},{%8,%9},{%0,%1,%2,%3};"                           \
        : "+f"((c)[0]), "+f"((c)[1]), "+f"((c)[2]), "+f"((c)[3])                       \
        : "r"(a0), "r"(a1), "r"(a2), "r"(a3), "r"(b0), "r"(b1))

static __device__ __forceinline__ void cp16(unsigned saddr, const void* g) {
    asm volatile("cp.async.ca.shared.global [%0], [%1], 16;\n" :: "r"(saddr), "l"(g));
}
static __device__ __forceinline__ void cp_commit() {
    asm volatile("cp.async.commit_group;\n");
}
static __device__ __forceinline__ void cp_wait1() {
    asm volatile("cp.async.wait_group 1;\n");
}
static __device__ __forceinline__ void cp_wait0() {
    asm volatile("cp.async.wait_group 0;\n");
}

// ---------------- CSR build ----------------
__global__ void init_kernel(int* deg, int* cnt, int* curr, int* curc, int* gcnt, int* gcur) {
    int i = blockIdx.x * blockDim.x + threadIdx.x;
    if (i < NNODES) { deg[i] = 0; cnt[i] = 0; curr[i] = 0; curc[i] = 0; }
    if (i < NGRAPH) { gcnt[i] = 0; gcur[i] = 0; }
    if (i == 0) g_is64 = 1;
}

__global__ void detect_kernel(const int* __restrict__ w, int twoE) {
    int i = blockIdx.x * blockDim.x + threadIdx.x;
    if (i < twoE && (i & 1) && w[i] != 0) g_is64 = 0;
}

__global__ void hist_kernel(const int* __restrict__ ew, int E, int* deg, int* cnt, int* gcnt) {
    int e = blockIdx.x * blockDim.x + threadIdx.x;
    if (e >= E) return;
    atomicAdd(&deg[edge_at(ew, e)], 1);
    int c = edge_at(ew, E + e);
    atomicAdd(&cnt[c], 1);
    atomicAdd(&gcnt[c / SNODES], 1);
}

static __device__ __forceinline__ int block_excl_scan256(int v) {
    __shared__ int ws[8];
    int lane = threadIdx.x & 31, wid = threadIdx.x >> 5;
    int x = v;
    #pragma unroll
    for (int o = 1; o < 32; o <<= 1) {
        int y = __shfl_up_sync(0xffffffffu, x, o);
        if (lane >= o) x += y;
    }
    if (lane == 31) ws[wid] = x;
    __syncthreads();
    if (threadIdx.x == 0) {
        int s = 0;
        #pragma unroll
        for (int w = 0; w < 8; ++w) { int t = ws[w]; ws[w] = s; s += t; }
    }
    __syncthreads();
    int r = x - v + ws[wid];
    __syncthreads();
    return r;
}

__global__ void scan_p1(const int* __restrict__ deg, const int* __restrict__ cnt,
                        int* __restrict__ bsum) {
    const int* in = blockIdx.y ? cnt : deg;
    int v = in[blockIdx.x * 256 + threadIdx.x];
    __shared__ int ws[8];
    int lane = threadIdx.x & 31, wid = threadIdx.x >> 5;
    #pragma unroll
    for (int o = 16; o > 0; o >>= 1) v += __shfl_down_sync(0xffffffffu, v, o);
    if (lane == 0) ws[wid] = v;
    __syncthreads();
    if (threadIdx.x == 0) {
        int s = 0;
        #pragma unroll
        for (int w = 0; w < 8; ++w) s += ws[w];
        bsum[blockIdx.y * (NBLK + 1) + blockIdx.x] = s;
    }
}

// scan block sums (2 rows) + per-graph edge counts, single block of 256 threads
__global__ void scan_p2(int* __restrict__ bsum, const int* __restrict__ gcnt,
                        int* __restrict__ goff) {
    int t = threadIdx.x;
    #pragma unroll 1
    for (int row = 0; row < 2; ++row) {
        int v = (t < NBLK) ? bsum[row * (NBLK + 1) + t] : 0;
        int e = block_excl_scan256(v);
        if (t < NBLK) bsum[row * (NBLK + 1) + t] = e;
        if (t == NBLK - 1) bsum[row * (NBLK + 1) + NBLK] = e + v;
        __syncthreads();
    }
    __shared__ int carry;
    if (t == 0) carry = 0;
    __syncthreads();
    #pragma unroll 1
    for (int chunk = 0; chunk < 4; ++chunk) {
        int i = chunk * 256 + t;
        int v = gcnt[i];
        int e = block_excl_scan256(v) + carry;
        goff[i] = e;
        if (t == 255) carry = e + v;
        __syncthreads();
    }
    if (t == 0) goff[NGRAPH] = carry;
}

__global__ void scan_p3(const int* __restrict__ deg, const int* __restrict__ cnt,
                        const int* __restrict__ bsum,
                        int* __restrict__ roff, int* __restrict__ coff,
                        float* __restrict__ dinv) {
    const int* in = blockIdx.y ? cnt : deg;
    int* out = blockIdx.y ? coff : roff;
    int i = blockIdx.x * 256 + threadIdx.x;
    int v = in[i];
    int e = block_excl_scan256(v) + bsum[blockIdx.y * (NBLK + 1) + blockIdx.x];
    out[i] = e;
    if (i == NNODES - 1) out[NNODES] = bsum[blockIdx.y * (NBLK + 1) + NBLK];
    if (blockIdx.y == 0)
        dinv[i] = (v > 0) ? rsqrtf((float)v) : 0.f;
}

__global__ void fill_kernel(const int* __restrict__ ew, int E,
                            const float* __restrict__ dinv,
                            const int* __restrict__ roff, const int* __restrict__ coff,
                            const int* __restrict__ goff, const int* __restrict__ cnt,
                            int* curr, int* curc, int* gcur,
                            int* __restrict__ rnbr, float* __restrict__ rw,
                            int* __restrict__ cnbr,
                            int* __restrict__ gsrc, float* __restrict__ gwt) {
    int e = blockIdx.x * blockDim.x + threadIdx.x;
    if (e >= E) return;
    int r = edge_at(ew, e);
    int c = edge_at(ew, E + e);
    float w = -(dinv[r] * dinv[c]);
    int p = roff[r] + atomicAdd(&curr[r], 1);
    rnbr[p] = c; rw[p] = w;
    int q = coff[c] + atomicAdd(&curc[c], 1);
    cnbr[q] = r;
    int gd = c / SNODES;
    int q2 = goff[gd] + atomicAdd(&gcur[gd], 1);
    gsrc[q2] = r;
    gwt[q2] = 1.0f / ((float)SNODES * (float)cnt[c]);
}

// ---------------- weight preconvert: both layers in one launch ----------------
__global__ void convw_kernel(const float* __restrict__ Wl1, const float* __restrict__ Wr1,
                             const float* __restrict__ Wl2, const float* __restrict__ Wr2,
                             unsigned* __restrict__ W1h, unsigned* __restrict__ W1l,
                             unsigned* __restrict__ W2h, unsigned* __restrict__ W2l) {
    int gi = blockIdx.x * 256 + threadIdx.x;   // over 2 * 512*512 u32
    int layer = gi >> 18;                      // 262144 u32 per layer
    int i = gi & 0x3FFFF;
    int o  = i >> 9;
    int ku = i & 511;
    const float* Wl = layer ? Wl2 : Wl1;
    const float* Wr = layer ? Wr2 : Wr1;
    const float* src = (ku < 256) ? (Wl + (size_t)o * 512 + ku * 2)
                                  : (Wr + (size_t)o * 512 + (ku - 256) * 2);
    unsigned lo;
    unsigned hi = pack_hi_lo(src[0], src[1], lo);
    if (layer) { W2h[i] = hi; W2l[i] = lo; }
    else       { W1h[i] = hi; W1l[i] = lo; }
}

// ---------------- lap + concat: fp32 [x|lap] -> g_A ; split -> Ah/Al cols 512:1024 ----------------
__global__ void lap_kernel(const float* __restrict__ x,
                           const int* __restrict__ roff,
                           const int* __restrict__ rnbr,
                           const float* __restrict__ rw,
                           float* __restrict__ A,
                           unsigned* __restrict__ Ah, unsigned* __restrict__ Al) {
    int gw   = (blockIdx.x * blockDim.x + threadIdx.x) >> 5;
    int lane = threadIdx.x & 31;
    if (gw >= NNODES) return;
    const float4* xi = (const float4*)(x + (size_t)gw * DFEAT);
    float4 a0 = xi[lane], a1 = xi[lane + 32];
    float4 s0 = a0, s1 = a1;
    int e = roff[gw], end = roff[gw + 1];
    for (; e < end; ++e) {
        int   c = rnbr[e];
        float w = rw[e];
        const float4* xc = (const float4*)(x + (size_t)c * DFEAT);
        s0 = f4fma(s0, w, xc[lane]);
        s1 = f4fma(s1, w, xc[lane + 32]);
    }
    float4* Af = (float4*)(A + (size_t)gw * 512);
    Af[lane]      = a0; Af[32 + lane] = a1;
    Af[64 + lane] = s0; Af[96 + lane] = s1;
    uint2* ph = (uint2*)(Ah + (size_t)gw * 512);
    uint2* pl = (uint2*)(Al + (size_t)gw * 512);
    unsigned l0, l1;
    uint2 h, l;
    h.x = pack_hi_lo(a0.x, a0.y, l0); h.y = pack_hi_lo(a0.z, a0.w, l1); l.x = l0; l.y = l1;
    ph[128 + lane] = h; pl[128 + lane] = l;
    h.x = pack_hi_lo(a1.x, a1.y, l0); h.y = pack_hi_lo(a1.z, a1.w, l1); l.x = l0; l.y = l1;
    ph[160 + lane] = h; pl[160 + lane] = l;
    h.x = pack_hi_lo(s0.x, s0.y, l0); h.y = pack_hi_lo(s0.z, s0.w, l1); l.x = l0; l.y = l1;
    ph[192 + lane] = h; pl[192 + lane] = l;
    h.x = pack_hi_lo(s1.x, s1.y, l0); h.y = pack_hi_lo(s1.z, s1.w, l1); l.x = l0; l.y = l1;
    ph[224 + lane] = h; pl[224 + lane] = l;
}

// ---------------- conv1 mean aggregation: fp32 in (g_A), split out (Ah/Al cols 0:512) ----------------
__global__ void agg1_kernel(const float* __restrict__ A,
                            unsigned* __restrict__ Ah, unsigned* __restrict__ Al,
                            const int* __restrict__ coff, const int* __restrict__ cnbr) {
    int gw   = (blockIdx.x * blockDim.x + threadIdx.x) >> 5;
    int lane = threadIdx.x & 31;
    if (gw >= NNODES) return;
    float acc[16];
    #pragma unroll
    for (int i = 0; i < 16; ++i) acc[i] = 0.f;
    int beg = coff[gw], end = coff[gw + 1];
    for (int e = beg; e < end; ++e) {
        const float4* p = (const float4*)(A + (size_t)cnbr[e] * 512);
        float4 v0 = p[2 * lane], v1 = p[2 * lane + 1];
        float4 v2 = p[64 + 2 * lane], v3 = p[64 + 2 * lane + 1];
        acc[0] += v0.x; acc[1] += v0.y; acc[2] += v0.z; acc[3] += v0.w;
        acc[4] += v1.x; acc[5] += v1.y; acc[6] += v1.z; acc[7] += v1.w;
        acc[8]  += v2.x; acc[9]  += v2.y; acc[10] += v2.z; acc[11] += v2.w;
        acc[12] += v3.x; acc[13] += v3.y; acc[14] += v3.z; acc[15] += v3.w;
    }
    int cnt = end - beg;
    float sc = 1.f / (float)(cnt > 0 ? cnt : 1);
    #pragma unroll
    for (int i = 0; i < 16; ++i) acc[i] *= sc;
    uint4 oh, ol;
    oh.x = pack_hi_lo(acc[0], acc[1], ol.x);
    oh.y = pack_hi_lo(acc[2], acc[3], ol.y);
    oh.z = pack_hi_lo(acc[4], acc[5], ol.z);
    oh.w = pack_hi_lo(acc[6], acc[7], ol.w);
    ((uint4*)Ah)[(size_t)gw * 128 + lane] = oh;
    ((uint4*)Al)[(size_t)gw * 128 + lane] = ol;
    oh.x = pack_hi_lo(acc[8],  acc[9],  ol.x);
    oh.y = pack_hi_lo(acc[10], acc[11], ol.y);
    oh.z = pack_hi_lo(acc[12], acc[13], ol.z);
    oh.w = pack_hi_lo(acc[14], acc[15], ol.w);
    ((uint4*)Ah)[(size_t)gw * 128 + 32 + lane] = oh;
    ((uint4*)Al)[(size_t)gw * 128 + 32 + lane] = ol;
}

// ---------------- cp.async 3-stage tensor-core GEMM ----------------
// C[M,512] = (Ah+Al)[M,1024] @ (Bh+Bl)[512,1024]^T + bias; 3-term MMA.
// smem per stage: 4 arrays x 128 rows x 12 u32 (8 payload + 4 pad) = 24KB; 3 stages = 72KB dynamic.
#define RSTR 12
#define STG  (4 * 128 * RSTR)
template <bool GELU, bool SPLIT>
__global__ void __launch_bounds__(256, 2) gemm_cp(
    const unsigned* __restrict__ Ah, const unsigned* __restrict__ Al,
    const unsigned* __restrict__ Bh, const unsigned* __restrict__ Bl,
    const float* __restrict__ bias,
    float* __restrict__ C, unsigned* __restrict__ Ch, unsigned* __restrict__ Cl) {
    extern __shared__ unsigned dyn[];
    const int t    = threadIdx.x;
    const int bm   = blockIdx.y * 128, bn = blockIdx.x * 128;
    const int lane = t & 31, warp = t >> 5;
    const int wm   = warp & 3, wn = warp >> 2;
    const int g    = lane >> 2, tq = lane & 3;

    float acc[2][8][4];
    #pragma unroll
    for (int i = 0; i < 2; ++i)
        #pragma unroll
        for (int j = 0; j < 8; ++j)
            #pragma unroll
            for (int q = 0; q < 4; ++q) acc[i][j][q] = 0.f;

    // cp.async: thread t copies one 16B chunk per array: row = t>>1, half = t&1
    const int crow = t >> 1, chalf = t & 1;
    const unsigned sbase = (unsigned)__cvta_generic_to_shared(dyn);
    const size_t gA = (size_t)(bm + crow) * 512 + chalf * 4;
    const size_t gB = (size_t)(bn + crow) * 512 + chalf * 4;
    const unsigned sdst = sbase + (crow * RSTR + chalf * 4) * 4;

    auto issue = [&](int ks, int buf) {
        unsigned d = sdst + buf * (STG * 4);
        size_t ko = (size_t)ks * 8;
        cp16(d,            Ah + gA + ko);
        cp16(d + 1536 * 4, Al + gA + ko);
        cp16(d + 3072 * 4, Bh + gB + ko);
        cp16(d + 4608 * 4, Bl + gB + ko);
        cp_commit();
    };

    auto compute = [&](int buf) {
        const unsigned* sAh = dyn + buf * STG;
        const unsigned* sAl = sAh + 1536;
        const unsigned* sBh = sAh + 3072;
        const unsigned* sBl = sAh + 4608;
        unsigned bh0[8], bh1[8], bl0[8], bl1[8];
        #pragma unroll
        for (int nt = 0; nt < 8; ++nt) {
            int n = (wn * 64 + nt * 8 + g) * RSTR + tq;
            bh0[nt] = sBh[n]; bh1[nt] = sBh[n + 4];
            bl0[nt] = sBl[n]; bl1[nt] = sBl[n + 4];
        }
        #pragma unroll
        for (int mt = 0; mt < 2; ++mt) {
            int m0 = (wm * 32 + mt * 16 + g) * RSTR + tq;
            int m1 = m0 + 8 * RSTR;
            unsigned ah0 = sAh[m0], ah1 = sAh[m1], ah2 = sAh[m0 + 4], ah3 = sAh[m1 + 4];
            unsigned al0 = sAl[m0], al1 = sAl[m1], al2 = sAl[m0 + 4], al3 = sAl[m1 + 4];
            #pragma unroll
            for (int nt = 0; nt < 8; ++nt) {
                MMA_BF16(acc[mt][nt], ah0, ah1, ah2, ah3, bh0[nt], bh1[nt]);
                MMA_BF16(acc[mt][nt], ah0, ah1, ah2, ah3, bl0[nt], bl1[nt]);
                MMA_BF16(acc[mt][nt], al0, al1, al2, al3, bh0[nt], bh1[nt]);
            }
        }
    };

    issue(0, 0);
    issue(1, 1);
    #pragma unroll 1
    for (int s = 0; s < 64; ++s) {
        // Tail fix: for the last two iterations no new groups are issued, so
        // wait_group 1 would permit the group being computed to still be in
        // flight. Drain fully there.
        if (s < 62) cp_wait1(); else cp_wait0();
        __syncthreads();
        compute(s % 3);
        __syncthreads();
        if (s + 2 < 64) issue(s + 2, (s + 2) % 3);
    }

    #pragma unroll
    for (int mt = 0; mt < 2; ++mt) {
        int r0 = bm + wm * 32 + mt * 16 + g;
        #pragma unroll
        for (int nt = 0; nt < 8; ++nt) {
            int cc = bn + wn * 64 + nt * 8 + tq * 2;
            float b0v = bias[cc], b1v = bias[cc + 1];
            float v0 = acc[mt][nt][0] + b0v;
            float v1 = acc[mt][nt][1] + b1v;
            float v2 = acc[mt][nt][2] + b0v;
            float v3 = acc[mt][nt][3] + b1v;
            if (GELU) {
                v0 = 0.5f * v0 * (1.0f + erff(v0 * 0.70710678118654752f));
                v1 = 0.5f * v1 * (1.0f + erff(v1 * 0.70710678118654752f));
                v2 = 0.5f * v2 * (1.0f + erff(v2 * 0.70710678118654752f));
                v3 = 0.5f * v3 * (1.0f + erff(v3 * 0.70710678118654752f));
            }
            if (SPLIT) {
                unsigned lo;
                unsigned hi = pack_hi_lo(v0, v1, lo);
                Ch[(size_t)r0 * 256 + (cc >> 1)] = hi;
                Cl[(size_t)r0 * 256 + (cc >> 1)] = lo;
                hi = pack_hi_lo(v2, v3, lo);
                Ch[(size_t)(r0 + 8) * 256 + (cc >> 1)] = hi;
                Cl[(size_t)(r0 + 8) * 256 + (cc >> 1)] = lo;
            } else {
                *(float2*)(C + (size_t)r0 * GD + cc)       = make_float2(v0, v1);
                *(float2*)(C + (size_t)(r0 + 8) * GD + cc) = make_float2(v2, v3);
            }
        }
    }
}

// ---------------- fused conv2-aggregation + pooling ----------------
__global__ void graphagg_kernel(const unsigned* __restrict__ Hh, const unsigned* __restrict__ Hl,
                                const int* __restrict__ goff, const int* __restrict__ gsrc,
                                const float* __restrict__ gwt,
                                unsigned* __restrict__ A2h, unsigned* __restrict__ A2l) {
    int gidx = blockIdx.x;
    int t = threadIdx.x;
    float acc0 = 0.f, acc1 = 0.f, p0 = 0.f, p1 = 0.f;
    int beg = goff[gidx], end = goff[gidx + 1];
    for (int e = beg; e < end; ++e) {
        int src = gsrc[e];
        float w = gwt[e];
        float2 f = unpk2(Hh[(size_t)src * 256 + t], Hl[(size_t)src * 256 + t]);
        acc0 = fmaf(w, f.x, acc0);
        acc1 = fmaf(w, f.y, acc1);
    }
    size_t base = (size_t)gidx * SNODES * 256 + t;
    #pragma unroll 4
    for (int s = 0; s < SNODES; ++s) {
        float2 f = unpk2(Hh[base + (size_t)s * 256], Hl[base + (size_t)s * 256]);
        p0 += f.x; p1 += f.y;
    }
    const float inv = 1.0f / (float)SNODES;
    unsigned lo;
    unsigned hi = pack_hi_lo(acc0, acc1, lo);
    A2h[(size_t)gidx * 512 + t] = hi;
    A2l[(size_t)gidx * 512 + t] = lo;
    hi = pack_hi_lo(p0 * inv, p1 * inv, lo);
    A2h[(size_t)gidx * 512 + 256 + t] = hi;
    A2l[(size_t)gidx * 512 + 256 + t] = lo;
}

// ---------------- launcher ----------------
extern "C" void kernel_launch(void* const* d_in, const int* in_sizes, int n_in,
                              void* d_out, int out_size) {
    const float* x   = (const float*)d_in[0];
    const int*   ew  = (const int*)  d_in[1];
    const float* Wl1 = (const float*)d_in[2];
    const float* Wr1 = (const float*)d_in[3];
    const float* b1  = (const float*)d_in[4];
    const float* Wl2 = (const float*)d_in[5];
    const float* Wr2 = (const float*)d_in[6];
    const float* b2  = (const float*)d_in[7];
    int E = in_sizes[1] / 2;

    float *A, *rw, *dinv, *gwt;
    unsigned *Ah, *Al, *Hh, *Hl, *A2h, *A2l, *W1h, *W1l, *W2h, *W2l;
    int *deg, *cnt, *roff, *coff, *curr, *curc, *rnbr, *cnbr, *bsum;
    int *gcnt, *gcur, *goff, *gsrc;
    cudaGetSymbolAddress((void**)&A,    g_A);
    cudaGetSymbolAddress((void**)&Ah,   g_Ah);
    cudaGetSymbolAddress((void**)&Al,   g_Al);
    cudaGetSymbolAddress((void**)&Hh,   g_Hh);
    cudaGetSymbolAddress((void**)&Hl,   g_Hl);
    cudaGetSymbolAddress((void**)&A2h,  g_A2h);
    cudaGetSymbolAddress((void**)&A2l,  g_A2l);
    cudaGetSymbolAddress((void**)&W1h,  g_W1h);
    cudaGetSymbolAddress((void**)&W1l,  g_W1l);
    cudaGetSymbolAddress((void**)&W2h,  g_W2h);
    cudaGetSymbolAddress((void**)&W2l,  g_W2l);
    cudaGetSymbolAddress((void**)&rw,   g_rw);
    cudaGetSymbolAddress((void**)&dinv, g_dinv);
    cudaGetSymbolAddress((void**)&deg,  g_deg);
    cudaGetSymbolAddress((void**)&cnt,  g_cnt);
    cudaGetSymbolAddress((void**)&roff, g_roff);
    cudaGetSymbolAddress((void**)&coff, g_coff);
    cudaGetSymbolAddress((void**)&curr, g_curr);
    cudaGetSymbolAddress((void**)&curc, g_curc);
    cudaGetSymbolAddress((void**)&rnbr, g_rnbr);
    cudaGetSymbolAddress((void**)&cnbr, g_cnbr);
    cudaGetSymbolAddress((void**)&bsum, g_bsum);
    cudaGetSymbolAddress((void**)&gcnt, g_gcnt);
    cudaGetSymbolAddress((void**)&gcur, g_gcur);
    cudaGetSymbolAddress((void**)&goff, g_goff);
    cudaGetSymbolAddress((void**)&gsrc, g_gsrc);
    cudaGetSymbolAddress((void**)&gwt,  g_gwt);

    // no static guards (harness rule) — set attributes unconditionally
    cudaFuncSetAttribute(gemm_cp<true, true>,
                         cudaFuncAttributeMaxDynamicSharedMemorySize, 3 * STG * 4);
    cudaFuncSetAttribute(gemm_cp<false, false>,
                         cudaFuncAttributeMaxDynamicSharedMemorySize, 3 * STG * 4);
    const int SMEMB = 3 * STG * 4;   // 73728

    int eb = (E + 255) / 256;

    // launch 1-3
    init_kernel<<<(NNODES + 255) / 256, 256>>>(deg, cnt, curr, curc, gcnt, gcur);
    detect_kernel<<<(2 * E + 255) / 256, 256>>>(ew, 2 * E);
    hist_kernel<<<eb, 256>>>(ew, E, deg, cnt, gcnt);
    // launch 4: DUMMY gemm1 for ncu attribution (ncu profiles the 4th launch).
    // Reads persistent scratch (zero-init device globals on run 1); its output
    // is fully overwritten by the real gemm1 below -> deterministic final out.
    gemm_cp<true, true><<<dim3(4, NNODES / 128), 256, SMEMB>>>(
        Ah, Al, W1h, W1l, b1, nullptr, Hh, Hl);
    // CSR
    scan_p1<<<dim3(NBLK, 2), 256>>>(deg, cnt, bsum);
    scan_p2<<<1, 256>>>(bsum, gcnt, goff);
    scan_p3<<<dim3(NBLK, 2), 256>>>(deg, cnt, bsum, roff, coff, dinv);
    fill_kernel<<<eb, 256>>>(ew, E, dinv, roff, coff, goff, cnt,
                             curr, curc, gcur, rnbr, rw, cnbr, gsrc, gwt);
    // weights -> split bf16
    convw_kernel<<<2048, 256>>>(Wl1, Wr1, Wl2, Wr2, W1h, W1l, W2h, W2l);
    // lap + concat (fp32 + split)
    lap_kernel<<<NNODES / 8, 256>>>(x, roff, rnbr, rw, A, Ah, Al);
    // conv1 mean aggregation (fp32 in, split out)
    agg1_kernel<<<NNODES / 8, 256>>>(A, Ah, Al, coff, cnbr);
    // conv1 GEMM + bias + GELU -> split h
    gemm_cp<true, true><<<dim3(4, NNODES / 128), 256, SMEMB>>>(
        Ah, Al, W1h, W1l, b1, nullptr, Hh, Hl);
    // fused conv2-aggregation + pooling -> split A2
    graphagg_kernel<<<NGRAPH, 256>>>(Hh, Hl, goff, gsrc, gwt, A2h, A2l);
    // conv2 GEMM + bias -> out fp32
    gemm_cp<false, false><<<dim3(4, NGRAPH / 128), 256, SMEMB>>>(
        A2h, A2l, W2h, W2l, b2, (float*)d_out, nullptr, nullptr);
}

// round 7
// speedup vs baseline: 1.7764x; 1.7764x over previous
#include <cuda_runtime.h>
#include <cuda_bf16.h>
#include <math.h>

#define NNODES 49152
#define NEDGES 196608
#define NGRAPH 1024
#define SNODES 48
#define DFEAT  256
#define GD     512
#define NBLK   192      // NNODES / 256

// ---------------- scratch (static __device__: no allocations allowed) ----------------
// Split arrays use k-interleaved chunk order: per 8-u32 chunk, u32 o holds kpair
// inv(o) with layout [kp0,kp4,kp1,kp5,kp2,kp6,kp3,kp7] (MMA-fragment-ready).
__device__ float    g_A [(size_t)NNODES * 512];   // fp32 [x | lap]
__device__ unsigned g_Ah[(size_t)NNODES * 512];   // split A: cols 0:512 mean1, 512:768 x, 768:1024 lap
__device__ unsigned g_Al[(size_t)NNODES * 512];
__device__ unsigned g_Hh[(size_t)NNODES * 256];   // h [N,512] split
__device__ unsigned g_Hl[(size_t)NNODES * 256];
__device__ unsigned g_A2h[(size_t)NGRAPH * 512];  // A2 [B,1024]: [pool(mean2) | pool(h)]
__device__ unsigned g_A2l[(size_t)NGRAPH * 512];
__device__ unsigned g_W1h[512 * 512], g_W1l[512 * 512];
__device__ unsigned g_W2h[512 * 512], g_W2l[512 * 512];
__device__ int   g_deg [NNODES];
__device__ int   g_cnt [NNODES];
__device__ int   g_roff[NNODES + 1];
__device__ int   g_coff[NNODES + 1];
__device__ int   g_curr[NNODES];
__device__ int   g_curc[NNODES];
__device__ int   g_rnbr[NEDGES];
__device__ int   g_cnbr[NEDGES];
__device__ float g_rw  [NEDGES];
__device__ float g_dinv[NNODES];
__device__ int   g_bsum[2 * (NBLK + 1)];
__device__ int   g_gcnt[NGRAPH];
__device__ int   g_gcur[NGRAPH];
__device__ int   g_goff[NGRAPH + 1];
__device__ int   g_gsrc[NEDGES];
__device__ float g_gwt [NEDGES];
__device__ int   g_is64;

// ---------------- helpers ----------------
static __device__ __forceinline__ float4 f4fma(float4 a, float w, float4 b) {
    a.x = fmaf(w, b.x, a.x); a.y = fmaf(w, b.y, a.y);
    a.z = fmaf(w, b.z, a.z); a.w = fmaf(w, b.w, a.w); return a;
}
static __device__ __forceinline__ int edge_at(const int* __restrict__ w, int idx) {
    return g_is64 ? w[2 * idx] : w[idx];
}
// interleave kpair index p within its 8-u32 chunk: j<4 -> 2j, else 2(j-4)+1
static __device__ __forceinline__ int ilv(int p) {
    int j = p & 7;
    return (p & ~7) | ((j < 4) ? (j << 1) : (((j - 4) << 1) | 1));
}
static __device__ __forceinline__ unsigned pack_hi_lo(float x, float y, unsigned& lo) {
    __nv_bfloat16 hx = __float2bfloat16(x);
    __nv_bfloat16 hy = __float2bfloat16(y);
    float rx = x - __bfloat162float(hx);
    float ry = y - __bfloat162float(hy);
    __nv_bfloat16 lx = __float2bfloat16(rx);
    __nv_bfloat16 ly = __float2bfloat16(ry);
    lo = (unsigned)__bfloat16_as_ushort(lx) | ((unsigned)__bfloat16_as_ushort(ly) << 16);
    return (unsigned)__bfloat16_as_ushort(hx) | ((unsigned)__bfloat16_as_ushort(hy) << 16);
}
static __device__ __forceinline__ float2 unpk2(unsigned h, unsigned l) {
    __nv_bfloat162 hb = *reinterpret_cast<__nv_bfloat162*>(&h);
    __nv_bfloat162 lb = *reinterpret_cast<__nv_bfloat162*>(&l);
    return make_float2(__bfloat162float(hb.x) + __bfloat162float(lb.x),
                       __bfloat162float(hb.y) + __bfloat162float(lb.y));
}

#define MMA_BF16(c, a0, a1, a2, a3, b0, b1)                                           \
    asm volatile(                                                                      \
        "mma.sync.aligned.m16n8k16.row.col.f32.bf16.bf16.f32 "                         \
        "{%0,%1,%2,%3},{%4,%5,%6,%7},{%8,%9},{%0,%1,%2,%3};"                           \
        : "+f"((c)[0]), "+f"((c)[1]), "+f"((c)[2]), "+f"((c)[3])                       \
        : "r"(a0), "r"(a1), "r"(a2), "r"(a3), "r"(b0), "r"(b1))

static __device__ __forceinline__ void cp16(unsigned saddr, const void* g) {
    asm volatile("cp.async.ca.shared.global [%0], [%1], 16;\n" :: "r"(saddr), "l"(g));
}
static __device__ __forceinline__ void cp_commit() { asm volatile("cp.async.commit_group;\n"); }
static __device__ __forceinline__ void cp_wait2()  { asm volatile("cp.async.wait_group 2;\n"); }
static __device__ __forceinline__ void cp_wait1()  { asm volatile("cp.async.wait_group 1;\n"); }
static __device__ __forceinline__ void cp_wait0()  { asm volatile("cp.async.wait_group 0;\n"); }

// ---------------- CSR build ----------------
__global__ void init_kernel(int* deg, int* cnt, int* curr, int* curc, int* gcnt, int* gcur) {
    int i = blockIdx.x * blockDim.x + threadIdx.x;
    if (i < NNODES) { deg[i] = 0; cnt[i] = 0; curr[i] = 0; curc[i] = 0; }
    if (i < NGRAPH) { gcnt[i] = 0; gcur[i] = 0; }
    if (i == 0) g_is64 = 1;
}

__global__ void detect_kernel(const int* __restrict__ w, int twoE) {
    int i = blockIdx.x * blockDim.x + threadIdx.x;
    if (i < twoE && (i & 1) && w[i] != 0) g_is64 = 0;
}

__global__ void hist_kernel(const int* __restrict__ ew, int E, int* deg, int* cnt, int* gcnt) {
    int e = blockIdx.x * blockDim.x + threadIdx.x;
    if (e >= E) return;
    atomicAdd(&deg[edge_at(ew, e)], 1);
    int c = edge_at(ew, E + e);
    atomicAdd(&cnt[c], 1);
    atomicAdd(&gcnt[c / SNODES], 1);
}

static __device__ __forceinline__ int block_excl_scan256(int v) {
    __shared__ int ws[8];
    int lane = threadIdx.x & 31, wid = threadIdx.x >> 5;
    int x = v;
    #pragma unroll
    for (int o = 1; o < 32; o <<= 1) {
        int y = __shfl_up_sync(0xffffffffu, x, o);
        if (lane >= o) x += y;
    }
    if (lane == 31) ws[wid] = x;
    __syncthreads();
    if (threadIdx.x == 0) {
        int s = 0;
        #pragma unroll
        for (int w = 0; w < 8; ++w) { int t = ws[w]; ws[w] = s; s += t; }
    }
    __syncthreads();
    int r = x - v + ws[wid];
    __syncthreads();
    return r;
}

__global__ void scan_p1(const int* __restrict__ deg, const int* __restrict__ cnt,
                        int* __restrict__ bsum) {
    const int* in = blockIdx.y ? cnt : deg;
    int v = in[blockIdx.x * 256 + threadIdx.x];
    __shared__ int ws[8];
    int lane = threadIdx.x & 31, wid = threadIdx.x >> 5;
    #pragma unroll
    for (int o = 16; o > 0; o >>= 1) v += __shfl_down_sync(0xffffffffu, v, o);
    if (lane == 0) ws[wid] = v;
    __syncthreads();
    if (threadIdx.x == 0) {
        int s = 0;
        #pragma unroll
        for (int w = 0; w < 8; ++w) s += ws[w];
        bsum[blockIdx.y * (NBLK + 1) + blockIdx.x] = s;
    }
}

__global__ void scan_p2(int* __restrict__ bsum, const int* __restrict__ gcnt,
                        int* __restrict__ goff) {
    int t = threadIdx.x;
    #pragma unroll 1
    for (int row = 0; row < 2; ++row) {
        int v = (t < NBLK) ? bsum[row * (NBLK + 1) + t] : 0;
        int e = block_excl_scan256(v);
        if (t < NBLK) bsum[row * (NBLK + 1) + t] = e;
        if (t == NBLK - 1) bsum[row * (NBLK + 1) + NBLK] = e + v;
        __syncthreads();
    }
    __shared__ int carry;
    if (t == 0) carry = 0;
    __syncthreads();
    #pragma unroll 1
    for (int chunk = 0; chunk < 4; ++chunk) {
        int i = chunk * 256 + t;
        int v = gcnt[i];
        int e = block_excl_scan256(v) + carry;
        goff[i] = e;
        if (t == 255) carry = e + v;
        __syncthreads();
    }
    if (t == 0) goff[NGRAPH] = carry;
}

__global__ void scan_p3(const int* __restrict__ deg, const int* __restrict__ cnt,
                        const int* __restrict__ bsum,
                        int* __restrict__ roff, int* __restrict__ coff,
                        float* __restrict__ dinv) {
    const int* in = blockIdx.y ? cnt : deg;
    int* out = blockIdx.y ? coff : roff;
    int i = blockIdx.x * 256 + threadIdx.x;
    int v = in[i];
    int e = block_excl_scan256(v) + bsum[blockIdx.y * (NBLK + 1) + blockIdx.x];
    out[i] = e;
    if (i == NNODES - 1) out[NNODES] = bsum[blockIdx.y * (NBLK + 1) + NBLK];
    if (blockIdx.y == 0)
        dinv[i] = (v > 0) ? rsqrtf((float)v) : 0.f;
}

__global__ void fill_kernel(const int* __restrict__ ew, int E,
                            const float* __restrict__ dinv,
                            const int* __restrict__ roff, const int* __restrict__ coff,
                            const int* __restrict__ goff, const int* __restrict__ cnt,
                            int* curr, int* curc, int* gcur,
                            int* __restrict__ rnbr, float* __restrict__ rw,
                            int* __restrict__ cnbr,
                            int* __restrict__ gsrc, float* __restrict__ gwt) {
    int e = blockIdx.x * blockDim.x + threadIdx.x;
    if (e >= E) return;
    int r = edge_at(ew, e);
    int c = edge_at(ew, E + e);
    float w = -(dinv[r] * dinv[c]);
    int p = roff[r] + atomicAdd(&curr[r], 1);
    rnbr[p] = c; rw[p] = w;
    int q = coff[c] + atomicAdd(&curc[c], 1);
    cnbr[q] = r;
    int gd = c / SNODES;
    int q2 = goff[gd] + atomicAdd(&gcur[gd], 1);
    gsrc[q2] = r;
    gwt[q2] = 1.0f / ((float)SNODES * (float)cnt[c]);
}

// ---------------- weight preconvert (interleaved dest) ----------------
__global__ void convw_kernel(const float* __restrict__ Wl1, const float* __restrict__ Wr1,
                             const float* __restrict__ Wl2, const float* __restrict__ Wr2,
                             unsigned* __restrict__ W1h, unsigned* __restrict__ W1l,
                             unsigned* __restrict__ W2h, unsigned* __restrict__ W2l) {
    int gi = blockIdx.x * 256 + threadIdx.x;
    int layer = gi >> 18;
    int i = gi & 0x3FFFF;
    int o  = i >> 9;
    int ku = i & 511;
    const float* Wl = layer ? Wl2 : Wl1;
    const float* Wr = layer ? Wr2 : Wr1;
    const float* src = (ku < 256) ? (Wl + (size_t)o * 512 + ku * 2)
                                  : (Wr + (size_t)o * 512 + (ku - 256) * 2);
    unsigned lo;
    unsigned hi = pack_hi_lo(src[0], src[1], lo);
    int d = (o << 9) | ilv(ku);
    if (layer) { W2h[d] = hi; W2l[d] = lo; }
    else       { W1h[d] = hi; W1l[d] = lo; }
}

// ---------------- lap + concat ----------------
__global__ void lap_kernel(const float* __restrict__ x,
                           const int* __restrict__ roff,
                           const int* __restrict__ rnbr,
                           const float* __restrict__ rw,
                           float* __restrict__ A,
                           unsigned* __restrict__ Ah, unsigned* __restrict__ Al) {
    int gw   = (blockIdx.x * blockDim.x + threadIdx.x) >> 5;
    int lane = threadIdx.x & 31;
    if (gw >= NNODES) return;
    const float4* xi = (const float4*)(x + (size_t)gw * DFEAT);
    float4 a0 = xi[lane], a1 = xi[lane + 32];
    float4 s0 = a0, s1 = a1;
    int e = roff[gw], end = roff[gw + 1];
    for (; e < end; ++e) {
        int   c = rnbr[e];
        float w = rw[e];
        const float4* xc = (const float4*)(x + (size_t)c * DFEAT);
        s0 = f4fma(s0, w, xc[lane]);
        s1 = f4fma(s1, w, xc[lane + 32]);
    }
    float4* Af = (float4*)(A + (size_t)gw * 512);
    Af[lane]      = a0; Af[32 + lane] = a1;
    Af[64 + lane] = s0; Af[96 + lane] = s1;
    size_t rb = (size_t)gw * 512;
    unsigned lo, hi;
    int p;
    p = 256 + 2 * lane;
    hi = pack_hi_lo(a0.x, a0.y, lo); Ah[rb + ilv(p)]     = hi; Al[rb + ilv(p)]     = lo;
    hi = pack_hi_lo(a0.z, a0.w, lo); Ah[rb + ilv(p + 1)] = hi; Al[rb + ilv(p + 1)] = lo;
    p = 320 + 2 * lane;
    hi = pack_hi_lo(a1.x, a1.y, lo); Ah[rb + ilv(p)]     = hi; Al[rb + ilv(p)]     = lo;
    hi = pack_hi_lo(a1.z, a1.w, lo); Ah[rb + ilv(p + 1)] = hi; Al[rb + ilv(p + 1)] = lo;
    p = 384 + 2 * lane;
    hi = pack_hi_lo(s0.x, s0.y, lo); Ah[rb + ilv(p)]     = hi; Al[rb + ilv(p)]     = lo;
    hi = pack_hi_lo(s0.z, s0.w, lo); Ah[rb + ilv(p + 1)] = hi; Al[rb + ilv(p + 1)] = lo;
    p = 448 + 2 * lane;
    hi = pack_hi_lo(s1.x, s1.y, lo); Ah[rb + ilv(p)]     = hi; Al[rb + ilv(p)]     = lo;
    hi = pack_hi_lo(s1.z, s1.w, lo); Ah[rb + ilv(p + 1)] = hi; Al[rb + ilv(p + 1)] = lo;
}

// ---------------- conv1 mean aggregation ----------------
__global__ void agg1_kernel(const float* __restrict__ A,
                            unsigned* __restrict__ Ah, unsigned* __restrict__ Al,
                            const int* __restrict__ coff, const int* __restrict__ cnbr) {
    int gw   = (blockIdx.x * blockDim.x + threadIdx.x) >> 5;
    int lane = threadIdx.x & 31;
    if (gw >= NNODES) return;
    float acc[16];
    #pragma unroll
    for (int i = 0; i < 16; ++i) acc[i] = 0.f;
    int beg = coff[gw], end = coff[gw + 1];
    for (int e = beg; e < end; ++e) {
        const float4* p = (const float4*)(A + (size_t)cnbr[e] * 512);
        float4 v0 = p[2 * lane], v1 = p[2 * lane + 1];
        float4 v2 = p[64 + 2 * lane], v3 = p[64 + 2 * lane + 1];
        acc[0] += v0.x; acc[1] += v0.y; acc[2] += v0.z; acc[3] += v0.w;
        acc[4] += v1.x; acc[5] += v1.y; acc[6] += v1.z; acc[7] += v1.w;
        acc[8]  += v2.x; acc[9]  += v2.y; acc[10] += v2.z; acc[11] += v2.w;
        acc[12] += v3.x; acc[13] += v3.y; acc[14] += v3.z; acc[15] += v3.w;
    }
    int cnt = end - beg;
    float sc = 1.f / (float)(cnt > 0 ? cnt : 1);
    #pragma unroll
    for (int i = 0; i < 16; ++i) acc[i] *= sc;
    size_t rb = (size_t)gw * 512;
    #pragma unroll
    for (int q = 0; q < 4; ++q) {
        unsigned lo, hi;
        hi = pack_hi_lo(acc[2 * q], acc[2 * q + 1], lo);
        int p0 = 4 * lane + q;
        Ah[rb + ilv(p0)] = hi; Al[rb + ilv(p0)] = lo;
        hi = pack_hi_lo(acc[8 + 2 * q], acc[8 + 2 * q + 1], lo);
        int p1 = 128 + 4 * lane + q;
        Ah[rb + ilv(p1)] = hi; Al[rb + ilv(p1)] = lo;
    }
}

// ---------------- cp.async 4-stage tensor-core GEMM (interleaved global layout) ----------------
// stage = 4 arrays x 128 rows x 8 u32 = 16KB; 4 stages = 64KB dynamic smem.
#define STG4 4096
template <bool GELU, bool SPLIT>
__global__ void __launch_bounds__(256, 2) gemm_cp(
    const unsigned* __restrict__ Ah, const unsigned* __restrict__ Al,
    const unsigned* __restrict__ Bh, const unsigned* __restrict__ Bl,
    const float* __restrict__ bias,
    float* __restrict__ C, unsigned* __restrict__ Ch, unsigned* __restrict__ Cl) {
    extern __shared__ unsigned dyn[];
    const int t    = threadIdx.x;
    const int bm   = blockIdx.y * 128, bn = blockIdx.x * 128;
    const int lane = t & 31, warp = t >> 5;
    const int wm   = warp & 3, wn = warp >> 2;
    const int g    = lane >> 2, tq = lane & 3;

    float acc[2][8][4];
    #pragma unroll
    for (int i = 0; i < 2; ++i)
        #pragma unroll
        for (int j = 0; j < 8; ++j)
            #pragma unroll
            for (int q = 0; q < 4; ++q) acc[i][j][q] = 0.f;

    const int crow = t >> 1, chalf = t & 1;
    const unsigned sbase = (unsigned)__cvta_generic_to_shared(dyn);
    const size_t gA = (size_t)(bm + crow) * 512 + chalf * 4;
    const size_t gB = (size_t)(bn + crow) * 512 + chalf * 4;
    const unsigned sdst = sbase + (crow * 8 + chalf * 4) * 4;

    auto issue = [&](int ks, int buf) {
        unsigned d = sdst + buf * (STG4 * 4);
        size_t ko = (size_t)ks * 8;
        cp16(d,            Ah + gA + ko);
        cp16(d + 1024 * 4, Al + gA + ko);
        cp16(d + 2048 * 4, Bh + gB + ko);
        cp16(d + 3072 * 4, Bl + gB + ko);
        cp_commit();
    };

    auto compute = [&](int buf) {
        const uint2* sAh = (const uint2*)(dyn + buf * STG4);
        const uint2* sAl = (const uint2*)(dyn + buf * STG4 + 1024);
        const uint2* sBh = (const uint2*)(dyn + buf * STG4 + 2048);
        const uint2* sBl = (const uint2*)(dyn + buf * STG4 + 3072);
        uint2 bh[8], bl[8];
        #pragma unroll
        for (int nt = 0; nt < 8; ++nt) {
            int n = wn * 64 + nt * 8 + g;
            bh[nt] = sBh[n * 4 + tq];
            bl[nt] = sBl[n * 4 + tq];
        }
        #pragma unroll
        for (int mt = 0; mt < 2; ++mt) {
            int m = wm * 32 + mt * 16 + g;
            uint2 ah0 = sAh[m * 4 + tq], ah1 = sAh[(m + 8) * 4 + tq];
            uint2 al0 = sAl[m * 4 + tq], al1 = sAl[(m + 8) * 4 + tq];
            #pragma unroll
            for (int nt = 0; nt < 8; ++nt) {
                MMA_BF16(acc[mt][nt], ah0.x, ah1.x, ah0.y, ah1.y, bh[nt].x, bh[nt].y);
                MMA_BF16(acc[mt][nt], ah0.x, ah1.x, ah0.y, ah1.y, bl[nt].x, bl[nt].y);
                MMA_BF16(acc[mt][nt], al0.x, al1.x, al0.y, al1.y, bh[nt].x, bh[nt].y);
            }
        }
    };

    issue(0, 0); issue(1, 1); issue(2, 2);
    #pragma unroll 1
    for (int s = 0; s < 64; ++s) {
        if (s < 62) cp_wait2(); else if (s == 62) cp_wait1(); else cp_wait0();
        __syncthreads();
        compute(s & 3);
        if (s + 3 < 64) issue(s + 3, (s + 3) & 3);
    }

    #pragma unroll
    for (int mt = 0; mt < 2; ++mt) {
        int r0 = bm + wm * 32 + mt * 16 + g;
        #pragma unroll
        for (int nt = 0; nt < 8; ++nt) {
            int cc = bn + wn * 64 + nt * 8 + tq * 2;
            float b0v = bias[cc], b1v = bias[cc + 1];
            float v0 = acc[mt][nt][0] + b0v;
            float v1 = acc[mt][nt][1] + b1v;
            float v2 = acc[mt][nt][2] + b0v;
            float v3 = acc[mt][nt][3] + b1v;
            if (GELU) {
                v0 = 0.5f * v0 * (1.0f + erff(v0 * 0.70710678118654752f));
                v1 = 0.5f * v1 * (1.0f + erff(v1 * 0.70710678118654752f));
                v2 = 0.5f * v2 * (1.0f + erff(v2 * 0.70710678118654752f));
                v3 = 0.5f * v3 * (1.0f + erff(v3 * 0.70710678118654752f));
            }
            if (SPLIT) {
                int p = ilv(cc >> 1);
                unsigned lo;
                unsigned hi = pack_hi_lo(v0, v1, lo);
                Ch[(size_t)r0 * 256 + p] = hi;
                Cl[(size_t)r0 * 256 + p] = lo;
                hi = pack_hi_lo(v2, v3, lo);
                Ch[(size_t)(r0 + 8) * 256 + p] = hi;
                Cl[(size_t)(r0 + 8) * 256 + p] = lo;
            } else {
                *(float2*)(C + (size_t)r0 * GD + cc)       = make_float2(v0, v1);
                *(float2*)(C + (size_t)(r0 + 8) * GD + cc) = make_float2(v2, v3);
            }
        }
    }
}

// ---------------- fused conv2-aggregation + pooling ----------------
// Pure per-column op: the k-interleave permutation passes through unchanged
// (reads phys col t of H, writes phys col t / 256+t of A2).
__global__ void graphagg_kernel(const unsigned* __restrict__ Hh, const unsigned* __restrict__ Hl,
                                const int* __restrict__ goff, const int* __restrict__ gsrc,
                                const float* __restrict__ gwt,
                                unsigned* __restrict__ A2h, unsigned* __restrict__ A2l) {
    int gidx = blockIdx.x;
    int t = threadIdx.x;
    float acc0 = 0.f, acc1 = 0.f, p0 = 0.f, p1 = 0.f;
    int beg = goff[gidx], end = goff[gidx + 1];
    for (int e = beg; e < end; ++e) {
        int src = gsrc[e];
        float w = gwt[e];
        float2 f = unpk2(Hh[(size_t)src * 256 + t], Hl[(size_t)src * 256 + t]);
        acc0 = fmaf(w, f.x, acc0);
        acc1 = fmaf(w, f.y, acc1);
    }
    size_t base = (size_t)gidx * SNODES * 256 + t;
    #pragma unroll 4
    for (int s = 0; s < SNODES; ++s) {
        float2 f = unpk2(Hh[base + (size_t)s * 256], Hl[base + (size_t)s * 256]);
        p0 += f.x; p1 += f.y;
    }
    const float inv = 1.0f / (float)SNODES;
    unsigned lo;
    unsigned hi = pack_hi_lo(acc0, acc1, lo);
    A2h[(size_t)gidx * 512 + t] = hi;
    A2l[(size_t)gidx * 512 + t] = lo;
    hi = pack_hi_lo(p0 * inv, p1 * inv, lo);
    A2h[(size_t)gidx * 512 + 256 + t] = hi;
    A2l[(size_t)gidx * 512 + 256 + t] = lo;
}

// ---------------- launcher ----------------
extern "C" void kernel_launch(void* const* d_in, const int* in_sizes, int n_in,
                              void* d_out, int out_size) {
    const float* x   = (const float*)d_in[0];
    const int*   ew  = (const int*)  d_in[1];
    const float* Wl1 = (const float*)d_in[2];
    const float* Wr1 = (const float*)d_in[3];
    const float* b1  = (const float*)d_in[4];
    const float* Wl2 = (const float*)d_in[5];
    const float* Wr2 = (const float*)d_in[6];
    const float* b2  = (const float*)d_in[7];
    int E = in_sizes[1] / 2;

    float *A, *rw, *dinv, *gwt;
    unsigned *Ah, *Al, *Hh, *Hl, *A2h, *A2l, *W1h, *W1l, *W2h, *W2l;
    int *deg, *cnt, *roff, *coff, *curr, *curc, *rnbr, *cnbr, *bsum;
    int *gcnt, *gcur, *goff, *gsrc;
    cudaGetSymbolAddress((void**)&A,    g_A);
    cudaGetSymbolAddress((void**)&Ah,   g_Ah);
    cudaGetSymbolAddress((void**)&Al,   g_Al);
    cudaGetSymbolAddress((void**)&Hh,   g_Hh);
    cudaGetSymbolAddress((void**)&Hl,   g_Hl);
    cudaGetSymbolAddress((void**)&A2h,  g_A2h);
    cudaGetSymbolAddress((void**)&A2l,  g_A2l);
    cudaGetSymbolAddress((void**)&W1h,  g_W1h);
    cudaGetSymbolAddress((void**)&W1l,  g_W1l);
    cudaGetSymbolAddress((void**)&W2h,  g_W2h);
    cudaGetSymbolAddress((void**)&W2l,  g_W2l);
    cudaGetSymbolAddress((void**)&rw,   g_rw);
    cudaGetSymbolAddress((void**)&dinv, g_dinv);
    cudaGetSymbolAddress((void**)&deg,  g_deg);
    cudaGetSymbolAddress((void**)&cnt,  g_cnt);
    cudaGetSymbolAddress((void**)&roff, g_roff);
    cudaGetSymbolAddress((void**)&coff, g_coff);
    cudaGetSymbolAddress((void**)&curr, g_curr);
    cudaGetSymbolAddress((void**)&curc, g_curc);
    cudaGetSymbolAddress((void**)&rnbr, g_rnbr);
    cudaGetSymbolAddress((void**)&cnbr, g_cnbr);
    cudaGetSymbolAddress((void**)&bsum, g_bsum);
    cudaGetSymbolAddress((void**)&gcnt, g_gcnt);
    cudaGetSymbolAddress((void**)&gcur, g_gcur);
    cudaGetSymbolAddress((void**)&goff, g_goff);
    cudaGetSymbolAddress((void**)&gsrc, g_gsrc);
    cudaGetSymbolAddress((void**)&gwt,  g_gwt);

    cudaFuncSetAttribute(gemm_cp<true, true>,
                         cudaFuncAttributeMaxDynamicSharedMemorySize, 4 * STG4 * 4);
    cudaFuncSetAttribute(gemm_cp<false, false>,
                         cudaFuncAttributeMaxDynamicSharedMemorySize, 4 * STG4 * 4);
    const int SMEMB = 4 * STG4 * 4;   // 65536

    int eb = (E + 255) / 256;

    init_kernel<<<(NNODES + 255) / 256, 256>>>(deg, cnt, curr, curc, gcnt, gcur);
    detect_kernel<<<(2 * E + 255) / 256, 256>>>(ew, 2 * E);
    hist_kernel<<<eb, 256>>>(ew, E, deg, cnt, gcnt);
    scan_p1<<<dim3(NBLK, 2), 256>>>(deg, cnt, bsum);
    scan_p2<<<1, 256>>>(bsum, gcnt, goff);
    scan_p3<<<dim3(NBLK, 2), 256>>>(deg, cnt, bsum, roff, coff, dinv);
    fill_kernel<<<eb, 256>>>(ew, E, dinv, roff, coff, goff, cnt,
                             curr, curc, gcur, rnbr, rw, cnbr, gsrc, gwt);
    convw_kernel<<<2048, 256>>>(Wl1, Wr1, Wl2, Wr2, W1h, W1l, W2h, W2l);
    lap_kernel<<<NNODES / 8, 256>>>(x, roff, rnbr, rw, A, Ah, Al);
    agg1_kernel<<<NNODES / 8, 256>>>(A, Ah, Al, coff, cnbr);
    gemm_cp<true, true><<<dim3(4, NNODES / 128), 256, SMEMB>>>(
        Ah, Al, W1h, W1l, b1, nullptr, Hh, Hl);
    graphagg_kernel<<<NGRAPH, 256>>>(Hh, Hl, goff, gsrc, gwt, A2h, A2l);
    gemm_cp<false, false><<<dim3(4, NGRAPH / 128), 256, SMEMB>>>(
        A2h, A2l, W2h, W2l, b2, (float*)d_out, nullptr, nullptr);
}